// round 9
// baseline (speedup 1.0000x reference)
#include <cuda_runtime.h>

#define MT 64      // rows per block
#define HH 256     // hidden dim
#define RR 32      // rank
#define HSTR 260   // padded row stride for h in shared (16B-aligned, kills conflicts)

// Packed, alpha-folded col weights: [blk][k/4][r] = (col[4k..4k+3][r] * alpha[r])
__device__ float4 g_cpack[3][HH / 4][RR];

__device__ __forceinline__ float tanh_fast(float v) {
    float e = __expf(2.0f * v);
    return 1.0f - __fdividef(2.0f, e + 1.0f);
}

// packed dual-fp32 FMA (sm_103a FFMA2): acc.lo += a.lo*b.lo; acc.hi += a.hi*b.hi
#define FMA2(acc, a, b) \
    asm("fma.rn.f32x2 %0, %1, %2, %0;" : "+l"(acc) : "l"(a), "l"(b))

__device__ __forceinline__ float hadd2(unsigned long long v) {
    float lo, hi;
    asm("mov.b64 {%0, %1}, %2;" : "=f"(lo), "=f"(hi) : "l"(v));
    return lo + hi;
}

__global__ void pack_kernel(const float* __restrict__ col0, const float* __restrict__ col1,
                            const float* __restrict__ col2, const float* __restrict__ al0,
                            const float* __restrict__ al1, const float* __restrict__ al2)
{
    int idx = blockIdx.x * blockDim.x + threadIdx.x;   // over 3 * 64 * 32
    if (idx >= 3 * (HH / 4) * RR) return;
    int b  = idx / ((HH / 4) * RR);
    int k4 = (idx / RR) % (HH / 4);
    int r  = idx % RR;
    const float* c = (b == 0) ? col0 : (b == 1) ? col1 : col2;
    const float* a = (b == 0) ? al0 : (b == 1) ? al1 : al2;
    const float av = a[r];
    g_cpack[b][k4][r] = make_float4(c[(4 * k4 + 0) * RR + r] * av,
                                    c[(4 * k4 + 1) * RR + r] * av,
                                    c[(4 * k4 + 2) * RR + r] * av,
                                    c[(4 * k4 + 3) * RR + r] * av);
}

extern __shared__ float smem[];

__global__ void __launch_bounds__(256, 2) pinn_kernel(
    const float* __restrict__ gx, const float* __restrict__ gt,
    const float* __restrict__ start_w, const float* __restrict__ start_b,
    const float* __restrict__ end_w, const float* __restrict__ end_b,
    const float* __restrict__ row0, const float* __restrict__ row1,
    const float* __restrict__ row2,
    float* __restrict__ out)
{
    float* h  = smem;                    // MT * HSTR  (byte offset multiple of 16)
    float* u  = smem + MT * HSTR;        // MT * RR
    float* xs = u + MT * RR;             // MT
    float* ts = xs + MT;                 // MT

    const int tid  = threadIdx.x;
    const int base = blockIdx.x * MT;

    if (tid < MT)            xs[tid]      = gx[base + tid];
    else if (tid < 2 * MT)   ts[tid - MT] = gt[base + (tid - MT)];

    // ---- Phase A: h = tanh([x,t] @ start_w.T + start_b) ----
    const int j = tid;                       // thread owns hidden index j
    const float w0 = start_w[2 * j];
    const float w1 = start_w[2 * j + 1];
    const float sb = start_b[j];
    __syncthreads();

    #pragma unroll 4
    for (int m = 0; m < MT; m++) {
        h[m * HSTR + j] = tanh_fast(fmaf(xs[m], w0, fmaf(ts[m], w1, sb)));
    }
    __syncthreads();

    const int r  = tid & 31;   // rank index (lane)
    const int mb = tid >> 5;   // warp -> row group of 8

    #pragma unroll
    for (int blk = 0; blk < 3; blk++) {
        const float* rw = (blk == 0) ? row0 : (blk == 1) ? row1 : row2;
        const ulonglong2* cp =
            ((const ulonglong2*)g_cpack) + (size_t)blk * (HH / 4) * RR;

        // ---- Phase B: u[m][r] = sum_k h[m][k] * (col*alpha)[k][r]  (FMA2 over k-pairs)
        unsigned long long acc2[8];
        #pragma unroll
        for (int mm = 0; mm < 8; mm++) acc2[mm] = 0ull;

        #pragma unroll 2
        for (int k4 = 0; k4 < HH / 4; k4++) {
            const ulonglong2 cv = __ldg(&cp[k4 * RR + r]);   // 4 k-values for this r
            #pragma unroll
            for (int mm = 0; mm < 8; mm++) {
                const ulonglong2 hv =
                    *(const ulonglong2*)(h + (mb * 8 + mm) * HSTR + 4 * k4); // broadcast
                FMA2(acc2[mm], hv.x, cv.x);
                FMA2(acc2[mm], hv.y, cv.y);
            }
        }
        #pragma unroll
        for (int mm = 0; mm < 8; mm++)
            u[(mb * 8 + mm) * RR + r] = hadd2(acc2[mm]);
        __syncthreads();

        // ---- Phase C: h[m][j] = tanh(sum_r u[m][r] * row[j][r])  (FMA2 over r-pairs)
        unsigned long long rp[16];
        {
            const ulonglong2* rw2 = (const ulonglong2*)(rw + j * RR);
            #pragma unroll
            for (int i = 0; i < 8; i++) {
                const ulonglong2 t = __ldg(&rw2[i]);
                rp[2 * i]     = t.x;
                rp[2 * i + 1] = t.y;
            }
        }
        #pragma unroll 2
        for (int m0 = 0; m0 < MT; m0 += 4) {
            unsigned long long a0 = 0ull, a1 = 0ull, a2 = 0ull, a3 = 0ull;
            const ulonglong2* up0 = (const ulonglong2*)(u + (m0 + 0) * RR);
            const ulonglong2* up1 = (const ulonglong2*)(u + (m0 + 1) * RR);
            const ulonglong2* up2 = (const ulonglong2*)(u + (m0 + 2) * RR);
            const ulonglong2* up3 = (const ulonglong2*)(u + (m0 + 3) * RR);
            #pragma unroll
            for (int q = 0; q < 8; q++) {                 // 4 r-values per q
                const ulonglong2 v0 = up0[q];             // broadcast LDS.128
                const ulonglong2 v1 = up1[q];
                const ulonglong2 v2 = up2[q];
                const ulonglong2 v3 = up3[q];
                FMA2(a0, v0.x, rp[2 * q]); FMA2(a0, v0.y, rp[2 * q + 1]);
                FMA2(a1, v1.x, rp[2 * q]); FMA2(a1, v1.y, rp[2 * q + 1]);
                FMA2(a2, v2.x, rp[2 * q]); FMA2(a2, v2.y, rp[2 * q + 1]);
                FMA2(a3, v3.x, rp[2 * q]); FMA2(a3, v3.y, rp[2 * q + 1]);
            }
            h[(m0 + 0) * HSTR + j] = tanh_fast(hadd2(a0));
            h[(m0 + 1) * HSTR + j] = tanh_fast(hadd2(a1));
            h[(m0 + 2) * HSTR + j] = tanh_fast(hadd2(a2));
            h[(m0 + 3) * HSTR + j] = tanh_fast(hadd2(a3));
        }
        __syncthreads();
    }

    // ---- Phase D: out[m] = h[m] . end_w + end_b  (4 threads per row) ----
    const int m = tid >> 2;
    const int q = tid & 3;
    float s = 0.0f;
    #pragma unroll
    for (int jo = 0; jo < 64; jo += 4) {
        const int jj = q * 64 + jo;
        const float4 hv = *(const float4*)(h + m * HSTR + jj);
        const float4 wv = *(const float4*)(end_w + jj);
        s = fmaf(hv.x, wv.x, s);
        s = fmaf(hv.y, wv.y, s);
        s = fmaf(hv.z, wv.z, s);
        s = fmaf(hv.w, wv.w, s);
    }
    s += __shfl_xor_sync(0xffffffffu, s, 1);
    s += __shfl_xor_sync(0xffffffffu, s, 2);
    if (q == 0) out[base + m] = s + end_b[0];
}

extern "C" void kernel_launch(void* const* d_in, const int* in_sizes, int n_in,
                              void* d_out, int out_size) {
    const float* x  = (const float*)d_in[0];
    const float* t  = (const float*)d_in[1];
    const float* sw = (const float*)d_in[2];
    const float* sb = (const float*)d_in[3];
    const float* ew = (const float*)d_in[4];
    const float* eb = (const float*)d_in[5];
    const float* c0 = (const float*)d_in[6];
    const float* c1 = (const float*)d_in[7];
    const float* c2 = (const float*)d_in[8];
    const float* r0 = (const float*)d_in[9];
    const float* r1 = (const float*)d_in[10];
    const float* r2 = (const float*)d_in[11];
    const float* a0 = (const float*)d_in[12];
    const float* a1 = (const float*)d_in[13];
    const float* a2 = (const float*)d_in[14];
    float* out = (float*)d_out;

    const int N = in_sizes[0];

    // pre-pack alpha-folded col weights into __device__ scratch
    pack_kernel<<<(3 * (HH / 4) * RR + 255) / 256, 256>>>(c0, c1, c2, a0, a1, a2);

    const int smem_bytes = (MT * HSTR + MT * RR + 2 * MT) * (int)sizeof(float);
    cudaFuncSetAttribute(pinn_kernel, cudaFuncAttributeMaxDynamicSharedMemorySize,
                         smem_bytes);
    pinn_kernel<<<N / MT, 256, smem_bytes>>>(x, t, sw, sb, ew, eb,
                                             r0, r1, r2, out);
}

// round 10
// speedup vs baseline: 1.3941x; 1.3941x over previous
#include <cuda_runtime.h>

#define MT 64      // rows per block
#define HH 256     // hidden dim
#define RR 32      // rank
#define HSTR 260   // padded row stride for h in shared (16B aligned: 1040B)

// Packed, alpha-folded col weights: [blk][k4][rh][s] = float4 over k of col[k][2rh+s]*alpha
__device__ float4 g_cpkB[3][HH / 4][16][2];
// Transposed row weights: [blk][q][j] = float4(row[j][4q..4q+3])
__device__ float4 g_rwT[3][8][HH];

__device__ __forceinline__ float tanh_fast(float v) {
    float e = __expf(2.0f * v);
    return 1.0f - __fdividef(2.0f, e + 1.0f);
}

// packed dual-fp32 FMA (sm_103a FFMA2)
#define FMA2(acc, a, b) \
    asm("fma.rn.f32x2 %0, %1, %2, %0;" : "+l"(acc) : "l"(a), "l"(b))

__device__ __forceinline__ float hadd2(unsigned long long v) {
    float lo, hi;
    asm("mov.b64 {%0, %1}, %2;" : "=f"(lo), "=f"(hi) : "l"(v));
    return lo + hi;
}

__global__ void pack_kernel(const float* __restrict__ col0, const float* __restrict__ col1,
                            const float* __restrict__ col2, const float* __restrict__ row0,
                            const float* __restrict__ row1, const float* __restrict__ row2,
                            const float* __restrict__ al0, const float* __restrict__ al1,
                            const float* __restrict__ al2)
{
    int idx = blockIdx.x * blockDim.x + threadIdx.x;
    const int NC = 3 * (HH / 4) * 16 * 2;        // 6144 col-pack float4s
    if (idx < NC) {
        int b   = idx / ((HH / 4) * 32);
        int rem = idx % ((HH / 4) * 32);
        int k4  = rem / 32;
        int rh  = (rem % 32) >> 1;
        int s   = rem & 1;
        int r   = 2 * rh + s;
        const float* c = (b == 0) ? col0 : (b == 1) ? col1 : col2;
        const float* a = (b == 0) ? al0 : (b == 1) ? al1 : al2;
        const float av = a[r];
        g_cpkB[b][k4][rh][s] = make_float4(c[(4 * k4 + 0) * RR + r] * av,
                                           c[(4 * k4 + 1) * RR + r] * av,
                                           c[(4 * k4 + 2) * RR + r] * av,
                                           c[(4 * k4 + 3) * RR + r] * av);
        return;
    }
    idx -= NC;
    const int NR = 3 * 8 * HH;                   // 6144 row-pack float4s
    if (idx < NR) {
        int b = idx / (8 * HH);
        int q = (idx / HH) % 8;
        int j = idx % HH;
        const float* rw = (b == 0) ? row0 : (b == 1) ? row1 : row2;
        g_rwT[b][q][j] = make_float4(rw[j * RR + 4 * q + 0], rw[j * RR + 4 * q + 1],
                                     rw[j * RR + 4 * q + 2], rw[j * RR + 4 * q + 3]);
    }
}

extern __shared__ float smem[];

__global__ void __launch_bounds__(128, 3) pinn_kernel(
    const float* __restrict__ gx, const float* __restrict__ gt,
    const float* __restrict__ start_w, const float* __restrict__ start_b,
    const float* __restrict__ end_w, const float* __restrict__ end_b,
    float* __restrict__ out)
{
    float* h  = smem;                    // MT * HSTR
    float* u  = smem + MT * HSTR;        // MT * RR
    float* xs = u + MT * RR;             // MT
    float* ts = xs + MT;                 // MT

    const int tid  = threadIdx.x;        // 0..127
    const int base = blockIdx.x * MT;

    if (tid < MT) xs[tid] = gx[base + tid];
    else          ts[tid - MT] = gt[base + (tid - MT)];

    // ---- Phase A: h = tanh([x,t] @ start_w.T + start_b); thread owns j0=tid, j1=tid+128
    const int j0 = tid, j1 = tid + 128;
    const float w00 = start_w[2 * j0], w01 = start_w[2 * j0 + 1], b0 = start_b[j0];
    const float w10 = start_w[2 * j1], w11 = start_w[2 * j1 + 1], b1 = start_b[j1];
    __syncthreads();

    #pragma unroll 4
    for (int m = 0; m < MT; m++) {
        const float xm = xs[m], tm = ts[m];
        h[m * HSTR + j0] = tanh_fast(fmaf(xm, w00, fmaf(tm, w01, b0)));
        h[m * HSTR + j1] = tanh_fast(fmaf(xm, w10, fmaf(tm, w11, b1)));
    }
    __syncthreads();

    const int lane = tid & 31;
    const int wrp  = tid >> 5;           // 0..3
    const int g    = lane >> 4;          // row-group half within warp
    const int rh   = lane & 15;          // rank-pair index: r0=2rh, r1=2rh+1
    const int rowb = wrp * 16 + g * 8;   // this thread's 8 rows

    #pragma unroll
    for (int blk = 0; blk < 3; blk++) {
        // ---- Phase B: u[m][r] = sum_k h[m][k]*(col*alpha)[k][r]; 16 rows/warp, 2 r/lane
        const ulonglong2* cp = (const ulonglong2*)&g_cpkB[blk][0][0][0];
        unsigned long long accA[8], accB[8];
        #pragma unroll
        for (int mm = 0; mm < 8; mm++) { accA[mm] = 0ull; accB[mm] = 0ull; }

        #pragma unroll 2
        for (int k4 = 0; k4 < HH / 4; k4++) {
            const ulonglong2 cva = __ldg(&cp[(k4 * 16 + rh) * 2 + 0]);  // r0: (k0,k1),(k2,k3)
            const ulonglong2 cvb = __ldg(&cp[(k4 * 16 + rh) * 2 + 1]);  // r1
            #pragma unroll
            for (int mm = 0; mm < 8; mm++) {
                const ulonglong2 hv =
                    *(const ulonglong2*)(h + (rowb + mm) * HSTR + 4 * k4);
                FMA2(accA[mm], hv.x, cva.x);
                FMA2(accA[mm], hv.y, cva.y);
                FMA2(accB[mm], hv.x, cvb.x);
                FMA2(accB[mm], hv.y, cvb.y);
            }
        }
        #pragma unroll
        for (int mm = 0; mm < 8; mm++) {
            *(float2*)(u + (rowb + mm) * RR + 2 * rh) =
                make_float2(hadd2(accA[mm]), hadd2(accB[mm]));
        }
        __syncthreads();

        // ---- Phase C: h[m][j] = tanh(sum_r u[m][r]*row[j][r]); 2 j/thread, 2 m/iter
        unsigned long long rp0[16], rp1[16];
        {
            const ulonglong2* rt = (const ulonglong2*)&g_rwT[blk][0][0];
            #pragma unroll
            for (int q = 0; q < 8; q++) {
                const ulonglong2 v0 = __ldg(&rt[q * HH + j0]);  // lane-consecutive
                const ulonglong2 v1 = __ldg(&rt[q * HH + j1]);
                rp0[2 * q] = v0.x; rp0[2 * q + 1] = v0.y;
                rp1[2 * q] = v1.x; rp1[2 * q + 1] = v1.y;
            }
        }
        for (int m = 0; m < MT; m += 2) {
            unsigned long long a00 = 0ull, a01 = 0ull, a10 = 0ull, a11 = 0ull;
            const ulonglong2* up0 = (const ulonglong2*)(u + m * RR);
            const ulonglong2* up1 = (const ulonglong2*)(u + (m + 1) * RR);
            #pragma unroll
            for (int q = 0; q < 8; q++) {
                const ulonglong2 v0 = up0[q];   // broadcast LDS.128
                const ulonglong2 v1 = up1[q];
                FMA2(a00, v0.x, rp0[2 * q]); FMA2(a00, v0.y, rp0[2 * q + 1]);
                FMA2(a01, v0.x, rp1[2 * q]); FMA2(a01, v0.y, rp1[2 * q + 1]);
                FMA2(a10, v1.x, rp0[2 * q]); FMA2(a10, v1.y, rp0[2 * q + 1]);
                FMA2(a11, v1.x, rp1[2 * q]); FMA2(a11, v1.y, rp1[2 * q + 1]);
            }
            h[m * HSTR + j0]       = tanh_fast(hadd2(a00));
            h[m * HSTR + j1]       = tanh_fast(hadd2(a01));
            h[(m + 1) * HSTR + j0] = tanh_fast(hadd2(a10));
            h[(m + 1) * HSTR + j1] = tanh_fast(hadd2(a11));
        }
        __syncthreads();
    }

    // ---- Phase D: out[m] = h[m].end_w + end_b; warp covers 16 rows x 2 halves
    const int m  = wrp * 16 + (lane & 15);
    const int hf = lane >> 4;
    float s = 0.0f;
    #pragma unroll
    for (int jo = 0; jo < 128; jo += 4) {
        const int jj = hf * 128 + jo;
        const float4 hv = *(const float4*)(h + m * HSTR + jj);
        const float4 wv = *(const float4*)(end_w + jj);
        s = fmaf(hv.x, wv.x, s);
        s = fmaf(hv.y, wv.y, s);
        s = fmaf(hv.z, wv.z, s);
        s = fmaf(hv.w, wv.w, s);
    }
    s += __shfl_xor_sync(0xffffffffu, s, 16);
    if (hf == 0) out[base + m] = s + end_b[0];
}

extern "C" void kernel_launch(void* const* d_in, const int* in_sizes, int n_in,
                              void* d_out, int out_size) {
    const float* x  = (const float*)d_in[0];
    const float* t  = (const float*)d_in[1];
    const float* sw = (const float*)d_in[2];
    const float* sb = (const float*)d_in[3];
    const float* ew = (const float*)d_in[4];
    const float* eb = (const float*)d_in[5];
    const float* c0 = (const float*)d_in[6];
    const float* c1 = (const float*)d_in[7];
    const float* c2 = (const float*)d_in[8];
    const float* r0 = (const float*)d_in[9];
    const float* r1 = (const float*)d_in[10];
    const float* r2 = (const float*)d_in[11];
    const float* a0 = (const float*)d_in[12];
    const float* a1 = (const float*)d_in[13];
    const float* a2 = (const float*)d_in[14];
    float* out = (float*)d_out;

    const int N = in_sizes[0];

    const int npack = 3 * (HH / 4) * 16 * 2 + 3 * 8 * HH;   // 12288
    pack_kernel<<<(npack + 255) / 256, 256>>>(c0, c1, c2, r0, r1, r2, a0, a1, a2);

    const int smem_bytes = (MT * HSTR + MT * RR + 2 * MT) * (int)sizeof(float);
    cudaFuncSetAttribute(pinn_kernel, cudaFuncAttributeMaxDynamicSharedMemorySize,
                         smem_bytes);
    pinn_kernel<<<N / MT, 128, smem_bytes>>>(x, t, sw, sb, ew, eb, out);
}